// round 1
// baseline (speedup 1.0000x reference)
#include <cuda_runtime.h>
#include <cstdint>

#define H       64
#define INP     32
#define G4      256     // 4*H
#define TT      128
#define BM      56      // batch elements per CTA
#define BMP     60      // padded row width (floats), 240B -> 16B aligned rows
#define NTHR    448     // 64 units * 7 groups
#define BPT     8       // batch elements per thread

// shared memory layout (floats)
#define OFF_WIH   0                        // [32][256] transposed W_ih
#define OFF_WHH   (OFF_WIH + INP*G4)       // [64][256] transposed W_hh
#define OFF_BIAS  (OFF_WHH + H*G4)         // [256]
#define OFF_XS    (OFF_BIAS + G4)          // [2][32][BMP]
#define OFF_HS    (OFF_XS + 2*INP*BMP)     // [2][64][BMP]
#define SMEM_FLOATS (OFF_HS + 2*H*BMP)
#define SMEM_BYTES  (SMEM_FLOATS * 4)

__device__ __forceinline__ float fsig(float v) {
    // 1/(1+e^-v); extremes: e^-v -> inf => 0 ; e^-v -> 0 => 1. Safe.
    return __fdividef(1.0f, 1.0f + __expf(-v));
}
__device__ __forceinline__ float ftanh(float v) {
    // sign-safe tanh via exp(-2|v|) in (0,1]: no inf/inf NaN.
    float a = fabsf(v);
    float e = __expf(-2.0f * a);
    float r = __fdividef(1.0f - e, 1.0f + e);
    return copysignf(r, v);
}

__global__ void __launch_bounds__(NTHR, 1)
lstm_kernel(const float* __restrict__ x,
            const float* __restrict__ W_ih,
            const float* __restrict__ W_hh,
            const float* __restrict__ b_ih,
            const float* __restrict__ b_hh,
            const float* __restrict__ W_fc,
            const float* __restrict__ b_fc,
            float* __restrict__ out,
            int Btotal)
{
    extern __shared__ float sm[];
    float* wih_s  = sm + OFF_WIH;   // wih_s[j*256 + g] = W_ih[g*32 + j]
    float* whh_s  = sm + OFF_WHH;   // whh_s[j*256 + g] = W_hh[g*64 + j]
    float* bias_s = sm + OFF_BIAS;
    float* xs     = sm + OFF_XS;    // xs[buf*INP*BMP + j*BMP + b]
    float* hs     = sm + OFF_HS;    // hs[buf*H*BMP   + j*BMP + b]

    const int tid   = threadIdx.x;
    const int bbase = blockIdx.x * BM;
    const int k     = tid & 63;       // hidden unit
    const int grp   = tid >> 6;       // 0..6
    const int b0    = grp * BPT;      // batch offset within tile

    // ---- stage weights transposed into smem (one-time) ----
    for (int idx = tid; idx < G4 * INP; idx += NTHR) {
        int g = idx >> 5, j = idx & 31;
        wih_s[j * G4 + g] = W_ih[idx];
    }
    for (int idx = tid; idx < G4 * H; idx += NTHR) {
        int g = idx >> 6, j = idx & 63;
        whh_s[j * G4 + g] = W_hh[idx];
    }
    for (int idx = tid; idx < G4; idx += NTHR)
        bias_s[idx] = b_ih[idx] + b_hh[idx];
    // zero both h buffers (h0 = 0; padded lanes stay 0 forever harmlessly)
    for (int idx = tid; idx < 2 * H * BMP; idx += NTHR)
        hs[idx] = 0.0f;

    // ---- x loading: each thread owns one float4 per step ----
    const int lb = tid >> 3;                 // 0..55 : batch within tile
    const int iv = (tid & 7) * 4;            // 0,4,...,28 : input feature
    const bool bvalid = (bbase + lb) < Btotal;
    const float* xrow = x + (size_t)(bbase + lb) * TT * INP + iv;

    // prolog: stage t=0, prefetch t=1
    float4 xr = make_float4(0.f, 0.f, 0.f, 0.f);
    if (bvalid) xr = *(const float4*)xrow;
    xs[(0) * INP * BMP + (iv + 0) * BMP + lb] = xr.x;
    xs[(0) * INP * BMP + (iv + 1) * BMP + lb] = xr.y;
    xs[(0) * INP * BMP + (iv + 2) * BMP + lb] = xr.z;
    xs[(0) * INP * BMP + (iv + 3) * BMP + lb] = xr.w;
    xr = make_float4(0.f, 0.f, 0.f, 0.f);
    if (bvalid) xr = *(const float4*)(xrow + INP);   // t = 1
    __syncthreads();

    float c[BPT];
#pragma unroll
    for (int b = 0; b < BPT; ++b) c[b] = 0.0f;

    int p = 0;
    const float bi = bias_s[k];
    const float bf = bias_s[k + 64];
    const float bg = bias_s[k + 128];
    const float bo = bias_s[k + 192];

    for (int t = 0; t < TT; ++t) {
        float acc0[BPT], acc1[BPT], acc2[BPT], acc3[BPT];
#pragma unroll
        for (int b = 0; b < BPT; ++b) {
            acc0[b] = bi; acc1[b] = bf; acc2[b] = bg; acc3[b] = bo;
        }

        const float* xb = xs + p * INP * BMP;
        const float* hb = hs + p * H * BMP;

        // ---- input contribution: 32 features ----
#pragma unroll 1
        for (int j = 0; j < INP; j += 4) {
#pragma unroll
            for (int jj = 0; jj < 4; ++jj) {
                const int jc = j + jj;
                float wi = wih_s[jc * G4 + k];
                float wf = wih_s[jc * G4 + 64 + k];
                float wg = wih_s[jc * G4 + 128 + k];
                float wo = wih_s[jc * G4 + 192 + k];
                float4 va = *(const float4*)&xb[jc * BMP + b0];
                float4 vb = *(const float4*)&xb[jc * BMP + b0 + 4];
                float xv[BPT] = {va.x, va.y, va.z, va.w, vb.x, vb.y, vb.z, vb.w};
#pragma unroll
                for (int b = 0; b < BPT; ++b) {
                    acc0[b] = fmaf(wi, xv[b], acc0[b]);
                    acc1[b] = fmaf(wf, xv[b], acc1[b]);
                    acc2[b] = fmaf(wg, xv[b], acc2[b]);
                    acc3[b] = fmaf(wo, xv[b], acc3[b]);
                }
            }
        }

        // ---- recurrent contribution: 64 hidden ----
#pragma unroll 1
        for (int j = 0; j < H; j += 4) {
#pragma unroll
            for (int jj = 0; jj < 4; ++jj) {
                const int jc = j + jj;
                float wi = whh_s[jc * G4 + k];
                float wf = whh_s[jc * G4 + 64 + k];
                float wg = whh_s[jc * G4 + 128 + k];
                float wo = whh_s[jc * G4 + 192 + k];
                float4 va = *(const float4*)&hb[jc * BMP + b0];
                float4 vb = *(const float4*)&hb[jc * BMP + b0 + 4];
                float hv[BPT] = {va.x, va.y, va.z, va.w, vb.x, vb.y, vb.z, vb.w};
#pragma unroll
                for (int b = 0; b < BPT; ++b) {
                    acc0[b] = fmaf(wi, hv[b], acc0[b]);
                    acc1[b] = fmaf(wf, hv[b], acc1[b]);
                    acc2[b] = fmaf(wg, hv[b], acc2[b]);
                    acc3[b] = fmaf(wo, hv[b], acc3[b]);
                }
            }
        }

        // ---- activations + state update (c private in regs) ----
        float* hn = hs + (1 - p) * H * BMP + k * BMP + b0;
#pragma unroll
        for (int b = 0; b < BPT; ++b) {
            float ig = fsig(acc0[b]);
            float fg = fsig(acc1[b]);
            float gg = ftanh(acc2[b]);
            float og = fsig(acc3[b]);
            float cn = fmaf(fg, c[b], ig * gg);
            c[b] = cn;
            hn[b] = og * ftanh(cn);
        }

        // ---- stage x(t+1) into the other buffer, prefetch x(t+2) ----
        if (t + 1 < TT) {
            float* xn = xs + (1 - p) * INP * BMP;
            xn[(iv + 0) * BMP + lb] = xr.x;
            xn[(iv + 1) * BMP + lb] = xr.y;
            xn[(iv + 2) * BMP + lb] = xr.z;
            xn[(iv + 3) * BMP + lb] = xr.w;
            if (t + 2 < TT) {
                xr = make_float4(0.f, 0.f, 0.f, 0.f);
                if (bvalid) xr = *(const float4*)(xrow + (size_t)(t + 2) * INP);
            }
        }
        __syncthreads();
        p ^= 1;
    }

    // ---- final FC: out[b][o] = h_T[b] . W_fc[o] + b_fc[o] ----
    // final h lives in hs[p] (buffer written on last step, p flipped onto it)
    const int ob = tid >> 3;         // 0..55
    const int oo = tid & 7;          // 0..7
    if (ob < BM && (bbase + ob) < Btotal) {
        const float* hfin = hs + p * H * BMP;
        float a = b_fc[oo];
#pragma unroll 8
        for (int kk = 0; kk < H; ++kk)
            a = fmaf(hfin[kk * BMP + ob], W_fc[oo * H + kk], a);
        out[(size_t)(bbase + ob) * 8 + oo] = a;
    }
}

extern "C" void kernel_launch(void* const* d_in, const int* in_sizes, int n_in,
                              void* d_out, int out_size) {
    const float* x    = (const float*)d_in[0];
    const float* W_ih = (const float*)d_in[1];
    const float* W_hh = (const float*)d_in[2];
    const float* b_ih = (const float*)d_in[3];
    const float* b_hh = (const float*)d_in[4];
    const float* W_fc = (const float*)d_in[5];
    const float* b_fc = (const float*)d_in[6];
    float* out = (float*)d_out;

    const int B = in_sizes[0] / (TT * INP);   // 8192
    const int grid = (B + BM - 1) / BM;       // 147

    cudaFuncSetAttribute(lstm_kernel,
                         cudaFuncAttributeMaxDynamicSharedMemorySize,
                         SMEM_BYTES);
    lstm_kernel<<<grid, NTHR, SMEM_BYTES>>>(x, W_ih, W_hh, b_ih, b_hh,
                                            W_fc, b_fc, out, B);
}

// round 2
// speedup vs baseline: 1.2104x; 1.2104x over previous
#include <cuda_runtime.h>
#include <cstdint>

#define H       64
#define INP     32
#define NF      96      // INP + H unified feature count
#define TT      128
#define BM      56      // batch elements per CTA
#define BMP     60      // padded row width (floats), 240B rows (16B aligned)
#define NTHR    448     // 64 units * 7 groups
#define BPT     8       // batch elements per thread (4 packed pairs)

typedef unsigned long long ull;

// shared memory layout (floats)
#define OFF_W4    0                         // [96][64] float4 : {wi,wf,wg,wo}
#define OFF_B4    (OFF_W4 + NF*H*4)         // [64] float4
#define OFF_ST    (OFF_B4 + H*4)            // [2][96][BMP] rows 0..31=x, 32..95=h
#define SMEM_FLOATS (OFF_ST + 2*NF*BMP)
#define SMEM_BYTES  (SMEM_FLOATS * 4)

__device__ __forceinline__ ull bcast2(float w) {
    ull r; asm("mov.b64 %0, {%1, %1};" : "=l"(r) : "f"(w)); return r;
}
__device__ __forceinline__ ull pack2(float lo, float hi) {
    ull r; asm("mov.b64 %0, {%1, %2};" : "=l"(r) : "f"(lo), "f"(hi)); return r;
}
__device__ __forceinline__ void unpack2(ull v, float& lo, float& hi) {
    asm("mov.b64 {%0, %1}, %2;" : "=f"(lo), "=f"(hi) : "l"(v));
}
__device__ __forceinline__ void fma2(ull& d, ull a, ull b) {
    asm("fma.rn.f32x2 %0, %1, %2, %0;" : "+l"(d) : "l"(a), "l"(b));
}

__device__ __forceinline__ float fsig(float v) {
    return __fdividef(1.0f, 1.0f + __expf(-v));
}
__device__ __forceinline__ float ftanh(float v) {
    float a = fabsf(v);
    float e = __expf(-2.0f * a);
    float r = __fdividef(1.0f - e, 1.0f + e);
    return copysignf(r, v);
}

__global__ void __launch_bounds__(NTHR, 1)
lstm_kernel(const float* __restrict__ x,
            const float* __restrict__ W_ih,
            const float* __restrict__ W_hh,
            const float* __restrict__ b_ih,
            const float* __restrict__ b_hh,
            const float* __restrict__ W_fc,
            const float* __restrict__ b_fc,
            float* __restrict__ out,
            int Btotal)
{
    extern __shared__ float sm[];
    float* w4 = sm + OFF_W4;   // w4[(j*64+k)*4 + gate]
    float* b4 = sm + OFF_B4;   // b4[k*4 + gate]
    float* st = sm + OFF_ST;   // st[buf*NF*BMP + row*BMP + b]

    const int tid   = threadIdx.x;
    const int bbase = blockIdx.x * BM;
    const int k     = tid & 63;       // hidden unit
    const int grp   = tid >> 6;       // 0..6
    const int b0    = grp * BPT;      // batch offset within tile

    // ---- stage weights into packed-gate layout (one-time) ----
    // n over 96*256 source elems: j = feature, g = gate*64 + unit
    for (int n = tid; n < NF * 256; n += NTHR) {
        int j = n >> 8, g = n & 255;
        float v = (j < INP) ? W_ih[g * INP + j] : W_hh[g * H + (j - INP)];
        int kk = g & 63, gate = g >> 6;
        w4[(j * H + kk) * 4 + gate] = v;
    }
    for (int n = tid; n < 256; n += NTHR) {
        int kk = n & 63, gate = n >> 6;
        b4[kk * 4 + gate] = b_ih[gate * H + kk] + b_hh[gate * H + kk];
    }
    // zero both state buffers (h0 = 0; x rows overwritten below)
    for (int n = tid; n < 2 * NF * BMP; n += NTHR)
        st[n] = 0.0f;

    // ---- x loading: each thread owns one float4 per step ----
    const int lb = tid >> 3;                 // 0..55 : batch within tile
    const int iv = (tid & 7) * 4;            // input feature base
    const bool bvalid = (bbase + lb) < Btotal;
    const float* xrow = x + (size_t)(bbase + lb) * TT * INP + iv;

    // prolog: stage t=0 into buf0 rows 0..31, prefetch t=1
    float4 xr = make_float4(0.f, 0.f, 0.f, 0.f);
    if (bvalid) xr = *(const float4*)xrow;
    st[(iv + 0) * BMP + lb] = xr.x;
    st[(iv + 1) * BMP + lb] = xr.y;
    st[(iv + 2) * BMP + lb] = xr.z;
    st[(iv + 3) * BMP + lb] = xr.w;
    xr = make_float4(0.f, 0.f, 0.f, 0.f);
    if (bvalid) xr = *(const float4*)(xrow + INP);   // t = 1
    __syncthreads();

    float c[BPT];
#pragma unroll
    for (int b = 0; b < BPT; ++b) c[b] = 0.0f;

    // packed bias pairs
    const float4 bk = *(const float4*)&b4[k * 4];
    const ull bi2 = bcast2(bk.x), bf2 = bcast2(bk.y),
              bg2 = bcast2(bk.z), bo2 = bcast2(bk.w);

    const float* w4k = w4 + k * 4;   // stride NF rows of 64*4 floats

    int p = 0;
    for (int t = 0; t < TT; ++t) {
        ull a0[4], a1[4], a2[4], a3[4];
#pragma unroll
        for (int q = 0; q < 4; ++q) {
            a0[q] = bi2; a1[q] = bf2; a2[q] = bg2; a3[q] = bo2;
        }

        const float* sb = st + p * NF * BMP;

#pragma unroll 1
        for (int j = 0; j < NF; j += 4) {
#pragma unroll
            for (int jj = 0; jj < 4; ++jj) {
                const int jc = j + jj;
                float4 w = *(const float4*)&w4k[jc * (H * 4)];
                ull wi = bcast2(w.x), wf = bcast2(w.y),
                    wg = bcast2(w.z), wo = bcast2(w.w);
                ulonglong2 va = *(const ulonglong2*)&sb[jc * BMP + b0];
                ulonglong2 vb = *(const ulonglong2*)&sb[jc * BMP + b0 + 4];
                ull pr[4] = {va.x, va.y, vb.x, vb.y};
#pragma unroll
                for (int q = 0; q < 4; ++q) {
                    fma2(a0[q], wi, pr[q]);
                    fma2(a1[q], wf, pr[q]);
                    fma2(a2[q], wg, pr[q]);
                    fma2(a3[q], wo, pr[q]);
                }
            }
        }

        // ---- activations + state update (c private in regs) ----
        float* hn = st + (1 - p) * NF * BMP + (INP + k) * BMP + b0;
#pragma unroll
        for (int q = 0; q < 4; ++q) {
            float i0, i1, f0, f1, g0, g1, o0, o1;
            unpack2(a0[q], i0, i1);
            unpack2(a1[q], f0, f1);
            unpack2(a2[q], g0, g1);
            unpack2(a3[q], o0, o1);

            float ig = fsig(i0), fg = fsig(f0), gg = ftanh(g0), og = fsig(o0);
            float cn = fmaf(fg, c[2 * q], ig * gg);
            c[2 * q] = cn;
            float h0 = og * ftanh(cn);

            ig = fsig(i1); fg = fsig(f1); gg = ftanh(g1); og = fsig(o1);
            cn = fmaf(fg, c[2 * q + 1], ig * gg);
            c[2 * q + 1] = cn;
            float h1 = og * ftanh(cn);

            *(float2*)&hn[2 * q] = make_float2(h0, h1);
        }

        // ---- stage x(t+1) into the other buffer, prefetch x(t+2) ----
        if (t + 1 < TT) {
            float* xn = st + (1 - p) * NF * BMP;
            xn[(iv + 0) * BMP + lb] = xr.x;
            xn[(iv + 1) * BMP + lb] = xr.y;
            xn[(iv + 2) * BMP + lb] = xr.z;
            xn[(iv + 3) * BMP + lb] = xr.w;
            if (t + 2 < TT) {
                xr = make_float4(0.f, 0.f, 0.f, 0.f);
                if (bvalid) xr = *(const float4*)(xrow + (size_t)(t + 2) * INP);
            }
        }
        __syncthreads();
        p ^= 1;
    }

    // ---- final FC: out[b][o] = h_T[b] . W_fc[o] + b_fc[o] ----
    const int ob = tid >> 3;         // 0..55
    const int oo = tid & 7;          // 0..7
    if (ob < BM && (bbase + ob) < Btotal) {
        const float* hfin = st + p * NF * BMP + INP * BMP;
        float a = b_fc[oo];
#pragma unroll 8
        for (int kk = 0; kk < H; ++kk)
            a = fmaf(hfin[kk * BMP + ob], W_fc[oo * H + kk], a);
        out[(size_t)(bbase + ob) * 8 + oo] = a;
    }
}

extern "C" void kernel_launch(void* const* d_in, const int* in_sizes, int n_in,
                              void* d_out, int out_size) {
    const float* x    = (const float*)d_in[0];
    const float* W_ih = (const float*)d_in[1];
    const float* W_hh = (const float*)d_in[2];
    const float* b_ih = (const float*)d_in[3];
    const float* b_hh = (const float*)d_in[4];
    const float* W_fc = (const float*)d_in[5];
    const float* b_fc = (const float*)d_in[6];
    float* out = (float*)d_out;

    const int B = in_sizes[0] / (TT * INP);   // 8192
    const int grid = (B + BM - 1) / BM;       // 147

    cudaFuncSetAttribute(lstm_kernel,
                         cudaFuncAttributeMaxDynamicSharedMemorySize,
                         SMEM_BYTES);
    lstm_kernel<<<grid, NTHR, SMEM_BYTES>>>(x, W_ih, W_hh, b_ih, b_hh,
                                            W_fc, b_fc, out, B);
}